// round 3
// baseline (speedup 1.0000x reference)
#include <cuda_runtime.h>
#include <math.h>
#include <stdint.h>

// ---------------------------------------------------------------------------
// Problem constants
// ---------------------------------------------------------------------------
#define BB 4
#define SS 1024
#define DD 1024
#define HH 16
#define DK 64
#define DFF 4096
#define MM (BB * SS)          // 4096 rows

// ---------------------------------------------------------------------------
// Scratch (no cudaMalloc allowed)
// ---------------------------------------------------------------------------
__device__ float g_xn [MM * DD];
__device__ float g_q  [MM * DD];
__device__ float g_k  [MM * DD];
__device__ float g_v  [MM * DD];
__device__ float g_ctx[MM * DD];
__device__ float g_xn2[MM * DD];
__device__ float g_h  [MM * DFF];

// ---------------------------------------------------------------------------
// LayerNorm: torch semantics — mean, std with ddof=1, eps added to std.
// ---------------------------------------------------------------------------
__global__ __launch_bounds__(256)
void layernorm_k(const float* __restrict__ x, float* __restrict__ y,
                 const float* __restrict__ alpha, const float* __restrict__ beta)
{
    __shared__ float red[256];
    const int r = blockIdx.x;
    const int t = threadIdx.x;
    const float4 v = reinterpret_cast<const float4*>(x + (size_t)r * DD)[t];

    red[t] = v.x + v.y + v.z + v.w;
    __syncthreads();
    #pragma unroll
    for (int o = 128; o > 0; o >>= 1) {
        if (t < o) red[t] += red[t + o];
        __syncthreads();
    }
    const float mean = red[0] * (1.0f / DD);
    __syncthreads();

    const float d0 = v.x - mean, d1 = v.y - mean, d2 = v.z - mean, d3 = v.w - mean;
    red[t] = d0 * d0 + d1 * d1 + d2 * d2 + d3 * d3;
    __syncthreads();
    #pragma unroll
    for (int o = 128; o > 0; o >>= 1) {
        if (t < o) red[t] += red[t + o];
        __syncthreads();
    }
    const float var = red[0] * (1.0f / (DD - 1));   // ddof = 1
    const float inv = 1.0f / (sqrtf(var) + 1e-6f);  // eps added to std
    const float a = alpha[0], b = beta[0];

    float4 o4;
    o4.x = a * d0 * inv + b;
    o4.y = a * d1 * inv + b;
    o4.z = a * d2 * inv + b;
    o4.w = a * d3 * inv + b;
    reinterpret_cast<float4*>(y + (size_t)r * DD)[t] = o4;
}

// ---------------------------------------------------------------------------
// tf32 helpers
// ---------------------------------------------------------------------------
__device__ __forceinline__ uint32_t f2tf32(float x) {
    uint32_t r;
    asm("cvt.rna.tf32.f32 %0, %1;" : "=r"(r) : "f"(x));
    return r;
}
__device__ __forceinline__ void split_tf32(float x, uint32_t& hi, uint32_t& lo) {
    hi = f2tf32(x);
    lo = f2tf32(x - __uint_as_float(hi));
}
__device__ __forceinline__ void mma_tf32(float c[4],
                                         uint32_t a0, uint32_t a1, uint32_t a2, uint32_t a3,
                                         uint32_t b0, uint32_t b1)
{
    asm volatile(
        "mma.sync.aligned.m16n8k8.row.col.f32.tf32.tf32.f32 "
        "{%0,%1,%2,%3}, {%4,%5,%6,%7}, {%8,%9}, {%0,%1,%2,%3};\n"
        : "+f"(c[0]), "+f"(c[1]), "+f"(c[2]), "+f"(c[3])
        : "r"(a0), "r"(a1), "r"(a2), "r"(a3), "r"(b0), "r"(b1));
}

// ---------------------------------------------------------------------------
// TF32 tensor-core GEMM with 3xTF32 precision recovery.
// C[M,N] = A[M,K] @ B[K,N] + bias[N] (+ReLU) (+residual)
// CTA tile 128x128, BK=16, 256 threads = 8 warps, warp tile 64x32.
// Smem: As[128][20] (pad-> conflict-free A-frag LDS), Bs[16][136].
// ---------------------------------------------------------------------------
#define AS_STRIDE 20
#define BS_STRIDE 136

__global__ __launch_bounds__(256)
void gemm_tf32_k(const float* __restrict__ A, const float* __restrict__ B,
                 const float* __restrict__ bias, const float* __restrict__ res,
                 float* __restrict__ C, int M, int N, int K, int do_relu)
{
    __shared__ float As[128 * AS_STRIDE];   // 10240 B
    __shared__ float Bs[16 * BS_STRIDE];    //  8704 B

    const int tid  = threadIdx.x;
    const int wid  = tid >> 5;
    const int lane = tid & 31;
    const int g    = lane >> 2;     // group row 0..7
    const int t4   = lane & 3;      // 0..3

    const int crow = blockIdx.y * 128;
    const int ccol = blockIdx.x * 128;
    const int wrow = (wid & 1) * 64;    // warp tile row
    const int wcol = (wid >> 1) * 32;   // warp tile col

    float c[4][4][4];   // [mf][nf][frag]
    #pragma unroll
    for (int mf = 0; mf < 4; mf++)
        #pragma unroll
        for (int nf = 0; nf < 4; nf++)
            #pragma unroll
            for (int i = 0; i < 4; i++) c[mf][nf][i] = 0.0f;

    // loader indices (512 float4 per tile, 2 per thread)
    const int la0 = tid * 2, la1 = tid * 2 + 1;

    for (int k0 = 0; k0 < K; k0 += 16) {
        // --- load A tile 128x16 ---
        #pragma unroll
        for (int li = 0; li < 2; li++) {
            const int l   = (li == 0) ? la0 : la1;
            const int row = l >> 2;
            const int c4  = (l & 3) * 4;
            const float4 v = *reinterpret_cast<const float4*>(
                A + (size_t)(crow + row) * K + k0 + c4);
            *reinterpret_cast<float4*>(&As[row * AS_STRIDE + c4]) = v;
        }
        // --- load B tile 16x128 ---
        #pragma unroll
        for (int li = 0; li < 2; li++) {
            const int l   = (li == 0) ? la0 : la1;
            const int row = l >> 5;
            const int c4  = (l & 31) * 4;
            const float4 v = *reinterpret_cast<const float4*>(
                B + (size_t)(k0 + row) * N + ccol + c4);
            *reinterpret_cast<float4*>(&Bs[row * BS_STRIDE + c4]) = v;
        }
        __syncthreads();

        #pragma unroll
        for (int ks = 0; ks < 16; ks += 8) {
            // A fragments: 4 m-frags, hi/lo
            uint32_t ah[4][4], al[4][4];
            #pragma unroll
            for (int mf = 0; mf < 4; mf++) {
                const int r0 = wrow + mf * 16 + g;
                split_tf32(As[(r0    ) * AS_STRIDE + ks + t4    ], ah[mf][0], al[mf][0]);
                split_tf32(As[(r0 + 8) * AS_STRIDE + ks + t4    ], ah[mf][1], al[mf][1]);
                split_tf32(As[(r0    ) * AS_STRIDE + ks + t4 + 4], ah[mf][2], al[mf][2]);
                split_tf32(As[(r0 + 8) * AS_STRIDE + ks + t4 + 4], ah[mf][3], al[mf][3]);
            }
            // B fragments: 4 n-frags, hi/lo
            uint32_t bh[4][2], bl[4][2];
            #pragma unroll
            for (int nf = 0; nf < 4; nf++) {
                const int c0 = wcol + nf * 8 + g;
                split_tf32(Bs[(ks + t4    ) * BS_STRIDE + c0], bh[nf][0], bl[nf][0]);
                split_tf32(Bs[(ks + t4 + 4) * BS_STRIDE + c0], bh[nf][1], bl[nf][1]);
            }
            // 3xTF32: hh + lh + hl
            #pragma unroll
            for (int mf = 0; mf < 4; mf++)
                #pragma unroll
                for (int nf = 0; nf < 4; nf++) {
                    mma_tf32(c[mf][nf], ah[mf][0], ah[mf][1], ah[mf][2], ah[mf][3],
                             bh[nf][0], bh[nf][1]);
                    mma_tf32(c[mf][nf], al[mf][0], al[mf][1], al[mf][2], al[mf][3],
                             bh[nf][0], bh[nf][1]);
                    mma_tf32(c[mf][nf], ah[mf][0], ah[mf][1], ah[mf][2], ah[mf][3],
                             bl[nf][0], bl[nf][1]);
                }
        }
        __syncthreads();
    }

    // --- epilogue ---
    #pragma unroll
    for (int mf = 0; mf < 4; mf++) {
        #pragma unroll
        for (int nf = 0; nf < 4; nf++) {
            const int row0 = crow + wrow + mf * 16 + g;
            const int col0 = ccol + wcol + nf * 8 + t4 * 2;
            float v0 = c[mf][nf][0] + bias[col0];
            float v1 = c[mf][nf][1] + bias[col0 + 1];
            float v2 = c[mf][nf][2] + bias[col0];
            float v3 = c[mf][nf][3] + bias[col0 + 1];
            if (do_relu) {
                v0 = fmaxf(v0, 0.0f); v1 = fmaxf(v1, 0.0f);
                v2 = fmaxf(v2, 0.0f); v3 = fmaxf(v3, 0.0f);
            }
            if (res) {
                const float2 r0 = *reinterpret_cast<const float2*>(
                    res + (size_t)row0 * N + col0);
                const float2 r1 = *reinterpret_cast<const float2*>(
                    res + (size_t)(row0 + 8) * N + col0);
                v0 += r0.x; v1 += r0.y; v2 += r1.x; v3 += r1.y;
            }
            *reinterpret_cast<float2*>(C + (size_t)row0 * N + col0)       = make_float2(v0, v1);
            *reinterpret_cast<float2*>(C + (size_t)(row0 + 8) * N + col0) = make_float2(v2, v3);
        }
    }
}

// ---------------------------------------------------------------------------
// Fused flash attention (fp32). One CTA = one (b,h) pair, 64 query rows.
// ---------------------------------------------------------------------------
__global__ __launch_bounds__(256)
void attn_k(const float* __restrict__ Q, const float* __restrict__ Kt,
            const float* __restrict__ V, const int* __restrict__ mask,
            float* __restrict__ O)
{
    __shared__ float Qs[64][65];
    __shared__ float Ks[32][65];
    __shared__ float Vs[32][65];
    __shared__ float Ps[64][33];

    const int bh = blockIdx.y;
    const int b  = bh >> 4;
    const int h  = bh & 15;
    const int q0 = blockIdx.x * 64;
    const int t  = threadIdx.x;
    const int r  = t >> 2;
    const int qd = t & 3;
    const int c0 = qd * 16;
    const int k0t = qd * 8;
    const float scale = 0.125f;     // 1/sqrt(64)

    const size_t qbase = ((size_t)(b * SS + q0)) * DD + h * DK;
    for (int i = t; i < 64 * 64; i += 256) {
        const int rr = i >> 6, cc = i & 63;
        Qs[rr][cc] = Q[qbase + (size_t)rr * DD + cc];
    }

    float m = -1e30f, l = 0.0f;
    float acc[16];
    #pragma unroll
    for (int i = 0; i < 16; i++) acc[i] = 0.0f;

    for (int kt = 0; kt < SS / 32; kt++) {
        __syncthreads();
        const size_t kb = ((size_t)(b * SS + kt * 32)) * DD + h * DK;
        for (int i = t; i < 32 * 64; i += 256) {
            const int rr = i >> 6, cc = i & 63;
            Ks[rr][cc] = Kt[kb + (size_t)rr * DD + cc];
            Vs[rr][cc] = V [kb + (size_t)rr * DD + cc];
        }
        __syncthreads();

        float s[8];
        #pragma unroll
        for (int kk = 0; kk < 8; kk++) s[kk] = 0.0f;
        for (int d = 0; d < 64; d++) {
            const float qv = Qs[r][d];
            #pragma unroll
            for (int kk = 0; kk < 8; kk++)
                s[kk] += qv * Ks[k0t + kk][d];
        }
        #pragma unroll
        for (int kk = 0; kk < 8; kk++) {
            const int kg = kt * 32 + k0t + kk;
            s[kk] = (mask[b * SS + kg] == 0) ? -1e9f : s[kk] * scale;
        }

        float mt = s[0];
        #pragma unroll
        for (int kk = 1; kk < 8; kk++) mt = fmaxf(mt, s[kk]);
        mt = fmaxf(mt, __shfl_xor_sync(0xffffffffu, mt, 1));
        mt = fmaxf(mt, __shfl_xor_sync(0xffffffffu, mt, 2));
        const float mn   = fmaxf(m, mt);
        const float corr = expf(m - mn);
        float ps = 0.0f;
        #pragma unroll
        for (int kk = 0; kk < 8; kk++) {
            const float p = expf(s[kk] - mn);
            Ps[r][k0t + kk] = p;
            ps += p;
        }
        ps += __shfl_xor_sync(0xffffffffu, ps, 1);
        ps += __shfl_xor_sync(0xffffffffu, ps, 2);
        l = l * corr + ps;
        m = mn;
        #pragma unroll
        for (int i = 0; i < 16; i++) acc[i] *= corr;
        __syncwarp();

        for (int k = 0; k < 32; k++) {
            const float pv = Ps[r][k];
            #pragma unroll
            for (int i = 0; i < 16; i++)
                acc[i] += pv * Vs[k][c0 + i];
        }
    }

    const float invl = 1.0f / l;
    const size_t ob = ((size_t)(b * SS + q0 + r)) * DD + h * DK + c0;
    #pragma unroll
    for (int i = 0; i < 16; i++) O[ob + i] = acc[i] * invl;
}

// ---------------------------------------------------------------------------
// Launch
// ---------------------------------------------------------------------------
extern "C" void kernel_launch(void* const* d_in, const int* in_sizes, int n_in,
                              void* d_out, int out_size)
{
    const float* x      = (const float*)d_in[0];
    const int*   mask   = (const int*)  d_in[1];
    const float* wq     = (const float*)d_in[2];
    const float* bq     = (const float*)d_in[3];
    const float* wk     = (const float*)d_in[4];
    const float* bk     = (const float*)d_in[5];
    const float* wv     = (const float*)d_in[6];
    const float* bv     = (const float*)d_in[7];
    const float* wo     = (const float*)d_in[8];
    const float* bo     = (const float*)d_in[9];
    const float* w1     = (const float*)d_in[10];
    const float* b1     = (const float*)d_in[11];
    const float* w2     = (const float*)d_in[12];
    const float* b2     = (const float*)d_in[13];
    const float* alpha1 = (const float*)d_in[14];
    const float* beta1  = (const float*)d_in[15];
    const float* alpha2 = (const float*)d_in[16];
    const float* beta2  = (const float*)d_in[17];
    float* out = (float*)d_out;

    float *xn, *q, *k, *v, *ctx, *xn2, *hbuf;
    cudaGetSymbolAddress((void**)&xn,   g_xn);
    cudaGetSymbolAddress((void**)&q,    g_q);
    cudaGetSymbolAddress((void**)&k,    g_k);
    cudaGetSymbolAddress((void**)&v,    g_v);
    cudaGetSymbolAddress((void**)&ctx,  g_ctx);
    cudaGetSymbolAddress((void**)&xn2,  g_xn2);
    cudaGetSymbolAddress((void**)&hbuf, g_h);

    // 1. LN1
    layernorm_k<<<MM, 256>>>(x, xn, alpha1, beta1);

    // 2-4. Q,K,V projections
    dim3 gP(DD / 128, MM / 128);
    gemm_tf32_k<<<gP, 256>>>(xn, wq, bq, nullptr, q, MM, DD, DD, 0);
    gemm_tf32_k<<<gP, 256>>>(xn, wk, bk, nullptr, k, MM, DD, DD, 0);
    gemm_tf32_k<<<gP, 256>>>(xn, wv, bv, nullptr, v, MM, DD, DD, 0);

    // 5. attention
    attn_k<<<dim3(SS / 64, BB * HH), 256>>>(q, k, v, mask, ctx);

    // 6. output projection + residual -> out holds x1
    gemm_tf32_k<<<gP, 256>>>(ctx, wo, bo, x, out, MM, DD, DD, 0);

    // 7. LN2
    layernorm_k<<<MM, 256>>>(out, xn2, alpha2, beta2);

    // 8. FFN1 + ReLU
    gemm_tf32_k<<<dim3(DFF / 128, MM / 128), 256>>>(xn2, w1, b1, nullptr, hbuf, MM, DFF, DD, 1);

    // 9. FFN2 + residual (in-place on out)
    gemm_tf32_k<<<gP, 256>>>(hbuf, w2, b2, out, out, MM, DD, DFF, 0);
}

// round 12
// speedup vs baseline: 2.8973x; 2.8973x over previous
#include <cuda_runtime.h>
#include <cuda_bf16.h>
#include <math.h>
#include <stdint.h>

#define BB 4
#define SS 1024
#define DD 1024
#define HH 16
#define DK 64
#define DFF 4096
#define MM (BB * SS)

// ---------------------------------------------------------------------------
// Scratch (bf16 pairs in uint32 arrays for 16B-aligned cp.async/uint4)
// ---------------------------------------------------------------------------
__device__ uint32_t g_xn_h [MM * DD / 2];
__device__ uint32_t g_xn_l [MM * DD / 2];
__device__ uint32_t g_q_h  [MM * DD / 2];
__device__ uint32_t g_q_l  [MM * DD / 2];
__device__ uint32_t g_k_h  [MM * DD / 2];
__device__ uint32_t g_k_l  [MM * DD / 2];
__device__ uint32_t g_v_h  [MM * DD / 2];
__device__ uint32_t g_ctx_h[MM * DD / 2];
__device__ uint32_t g_ctx_l[MM * DD / 2];
__device__ uint32_t g_xn2_h[MM * DD / 2];
__device__ uint32_t g_xn2_l[MM * DD / 2];
__device__ uint32_t g_h_h  [MM * DFF / 2];
__device__ uint32_t g_h_l  [MM * DFF / 2];
__device__ uint32_t g_wqt_h[DD * DD / 2];
__device__ uint32_t g_wqt_l[DD * DD / 2];
__device__ uint32_t g_wkt_h[DD * DD / 2];
__device__ uint32_t g_wkt_l[DD * DD / 2];
__device__ uint32_t g_wvt_h[DD * DD / 2];
__device__ uint32_t g_wvt_l[DD * DD / 2];
__device__ uint32_t g_wot_h[DD * DD / 2];
__device__ uint32_t g_wot_l[DD * DD / 2];
__device__ uint32_t g_w1t_h[DD * DFF / 2];
__device__ uint32_t g_w1t_l[DD * DFF / 2];
__device__ uint32_t g_w2t_h[DFF * DD / 2];
__device__ uint32_t g_w2t_l[DFF * DD / 2];

// ---------------------------------------------------------------------------
__device__ __forceinline__ void split_bf(float x, __nv_bfloat16& h, __nv_bfloat16& l)
{
    h = __float2bfloat16_rn(x);
    l = __float2bfloat16_rn(x - __bfloat162float(h));
}
__device__ __forceinline__ uint32_t pack2(__nv_bfloat16 a, __nv_bfloat16 b)
{
    __nv_bfloat162 p; p.x = a; p.y = b;
    return *reinterpret_cast<uint32_t*>(&p);
}

#define CPA16(dst, src) \
    asm volatile("cp.async.cg.shared.global [%0], [%1], 16;\n" \
                 :: "r"(dst), "l"(src))

__device__ __forceinline__ void mma_bf16(float c[4],
                                         uint32_t a0, uint32_t a1, uint32_t a2, uint32_t a3,
                                         uint32_t b0, uint32_t b1)
{
    asm volatile(
        "mma.sync.aligned.m16n8k16.row.col.f32.bf16.bf16.f32 "
        "{%0,%1,%2,%3}, {%4,%5,%6,%7}, {%8,%9}, {%0,%1,%2,%3};\n"
        : "+f"(c[0]), "+f"(c[1]), "+f"(c[2]), "+f"(c[3])
        : "r"(a0), "r"(a1), "r"(a2), "r"(a3), "r"(b0), "r"(b1));
}

// ---------------------------------------------------------------------------
// Weight prep: W[K][N] fp32 -> Wt_hi[N][K], Wt_lo[N][K] bf16 (transpose+split)
// ---------------------------------------------------------------------------
__global__ __launch_bounds__(256)
void wprep_k(const float* __restrict__ W, uint32_t* __restrict__ Th32,
             uint32_t* __restrict__ Tl32, int K, int N)
{
    __shared__ float tile[32][33];
    __nv_bfloat16* Th = reinterpret_cast<__nv_bfloat16*>(Th32);
    __nv_bfloat16* Tl = reinterpret_cast<__nv_bfloat16*>(Tl32);
    const int tid = threadIdx.x;
    const int tx = tid & 31, ty = tid >> 5;
    const int k0 = blockIdx.y * 32, n0 = blockIdx.x * 32;
    #pragma unroll
    for (int r = 0; r < 4; r++)
        tile[ty + r * 8][tx] = W[(size_t)(k0 + ty + r * 8) * N + n0 + tx];
    __syncthreads();
    #pragma unroll
    for (int r = 0; r < 4; r++) {
        const int n = n0 + ty + r * 8;
        const int k = k0 + tx;
        __nv_bfloat16 h, l;
        split_bf(tile[tx][ty + r * 8], h, l);
        Th[(size_t)n * K + k] = h;
        Tl[(size_t)n * K + k] = l;
    }
}

// ---------------------------------------------------------------------------
// LayerNorm (torch semantics) -> split bf16 output
// ---------------------------------------------------------------------------
__global__ __launch_bounds__(256)
void layernorm_k(const float* __restrict__ x,
                 uint32_t* __restrict__ yh, uint32_t* __restrict__ yl,
                 const float* __restrict__ alpha, const float* __restrict__ beta)
{
    __shared__ float red[256];
    const int r = blockIdx.x;
    const int t = threadIdx.x;
    const float4 v = reinterpret_cast<const float4*>(x + (size_t)r * DD)[t];

    red[t] = v.x + v.y + v.z + v.w;
    __syncthreads();
    #pragma unroll
    for (int o = 128; o > 0; o >>= 1) {
        if (t < o) red[t] += red[t + o];
        __syncthreads();
    }
    const float mean = red[0] * (1.0f / DD);
    __syncthreads();

    const float d0 = v.x - mean, d1 = v.y - mean, d2 = v.z - mean, d3 = v.w - mean;
    red[t] = d0 * d0 + d1 * d1 + d2 * d2 + d3 * d3;
    __syncthreads();
    #pragma unroll
    for (int o = 128; o > 0; o >>= 1) {
        if (t < o) red[t] += red[t + o];
        __syncthreads();
    }
    const float var = red[0] * (1.0f / (DD - 1));   // ddof = 1
    const float inv = 1.0f / (sqrtf(var) + 1e-6f);  // eps added to std
    const float a = alpha[0], b = beta[0];

    const float o0 = a * d0 * inv + b;
    const float o1 = a * d1 * inv + b;
    const float o2 = a * d2 * inv + b;
    const float o3 = a * d3 * inv + b;
    __nv_bfloat16 h0, l0, h1, l1, h2, l2, h3, l3;
    split_bf(o0, h0, l0); split_bf(o1, h1, l1);
    split_bf(o2, h2, l2); split_bf(o3, h3, l3);
    const size_t base = (size_t)r * (DD / 2) + t * 2;
    yh[base]     = pack2(h0, h1);
    yh[base + 1] = pack2(h2, h3);
    yl[base]     = pack2(l0, l1);
    yl[base + 1] = pack2(l2, l3);
}

// ---------------------------------------------------------------------------
// GEMM: C[M,N] = A[M,K] @ B^T[N,K] + bias (3-product 2-way bf16 split)
// 2-stage cp.async, XOR-swizzled smem. Outputs: fp32 C (+res) and/or bf16
// split Ch/Cl (Cl may be null -> plain bf16 out).
// ---------------------------------------------------------------------------
__global__ __launch_bounds__(256)
void gemm_bf16_k(const uint32_t* __restrict__ A_h, const uint32_t* __restrict__ A_l,
                 const uint32_t* __restrict__ B_h, const uint32_t* __restrict__ B_l,
                 const float* __restrict__ bias, const float* __restrict__ res,
                 float* __restrict__ C,
                 uint32_t* __restrict__ Ch, uint32_t* __restrict__ Cl,
                 int N, int K, int do_relu)
{
    __shared__ __align__(16) uint32_t As_h[2][128 * 8];
    __shared__ __align__(16) uint32_t As_l[2][128 * 8];
    __shared__ __align__(16) uint32_t Bs_h[2][128 * 8];
    __shared__ __align__(16) uint32_t Bs_l[2][128 * 8];

    const int tid  = threadIdx.x;
    const int wid  = tid >> 5;
    const int lane = tid & 31;
    const int g    = lane >> 2;
    const int t4   = lane & 3;

    const int crow = blockIdx.y * 128;
    const int ccol = blockIdx.x * 128;
    const int wrow = (wid & 1) * 64;
    const int wcol = (wid >> 1) * 32;

    const int Kw = K >> 1;
    const int nt = K >> 4;

    const int lrow  = tid >> 1;
    const int lquad = (tid & 1) << 2;
    const int lsw   = ((lrow >> 2) & 1) << 2;
    const int ldst  = lrow * 8 + (lquad ^ lsw);
    const uint32_t* gAh = A_h + (size_t)(crow + lrow) * Kw + lquad;
    const uint32_t* gAl = A_l + (size_t)(crow + lrow) * Kw + lquad;
    const uint32_t* gBh = B_h + (size_t)(ccol + lrow) * Kw + lquad;
    const uint32_t* gBl = B_l + (size_t)(ccol + lrow) * Kw + lquad;
    uint32_t sAh[2], sAl[2], sBh[2], sBl[2];
    #pragma unroll
    for (int b = 0; b < 2; b++) {
        sAh[b] = (uint32_t)__cvta_generic_to_shared(&As_h[b][ldst]);
        sAl[b] = (uint32_t)__cvta_generic_to_shared(&As_l[b][ldst]);
        sBh[b] = (uint32_t)__cvta_generic_to_shared(&Bs_h[b][ldst]);
        sBl[b] = (uint32_t)__cvta_generic_to_shared(&Bs_l[b][ldst]);
    }

    float c[4][4][4];
    #pragma unroll
    for (int mf = 0; mf < 4; mf++)
        #pragma unroll
        for (int nf = 0; nf < 4; nf++)
            #pragma unroll
            for (int i = 0; i < 4; i++) c[mf][nf][i] = 0.0f;

    int aoff[4], boff[4];
    #pragma unroll
    for (int mf = 0; mf < 4; mf++) {
        const int r0 = wrow + mf * 16 + g;
        aoff[mf] = (r0 << 3) + (t4 ^ (((r0 >> 2) & 1) << 2));
    }
    #pragma unroll
    for (int nf = 0; nf < 4; nf++) {
        const int n0 = wcol + nf * 8 + g;
        boff[nf] = (n0 << 3) + (t4 ^ (((n0 >> 2) & 1) << 2));
    }

    CPA16(sAh[0], gAh); CPA16(sAl[0], gAl);
    CPA16(sBh[0], gBh); CPA16(sBl[0], gBl);
    asm volatile("cp.async.commit_group;\n");

    for (int t = 0; t < nt; t++) {
        if (t + 1 < nt) {
            const int kw = (t + 1) * 8;
            const int nb = (t + 1) & 1;
            CPA16(sAh[nb], gAh + kw); CPA16(sAl[nb], gAl + kw);
            CPA16(sBh[nb], gBh + kw); CPA16(sBl[nb], gBl + kw);
        }
        asm volatile("cp.async.commit_group;\n");
        asm volatile("cp.async.wait_group 1;\n");
        __syncthreads();

        const int bi = t & 1;
        uint32_t ah[4][4], al[4][4];
        #pragma unroll
        for (int mf = 0; mf < 4; mf++) {
            const int o = aoff[mf];
            ah[mf][0] = As_h[bi][o];
            ah[mf][1] = As_h[bi][o + 64];
            ah[mf][2] = As_h[bi][o ^ 4];
            ah[mf][3] = As_h[bi][(o + 64) ^ 4];
            al[mf][0] = As_l[bi][o];
            al[mf][1] = As_l[bi][o + 64];
            al[mf][2] = As_l[bi][o ^ 4];
            al[mf][3] = As_l[bi][(o + 64) ^ 4];
        }
        uint32_t bh[4][2], bl[4][2];
        #pragma unroll
        for (int nf = 0; nf < 4; nf++) {
            const int o = boff[nf];
            bh[nf][0] = Bs_h[bi][o];
            bh[nf][1] = Bs_h[bi][o ^ 4];
            bl[nf][0] = Bs_l[bi][o];
            bl[nf][1] = Bs_l[bi][o ^ 4];
        }
        #pragma unroll
        for (int mf = 0; mf < 4; mf++)
            #pragma unroll
            for (int nf = 0; nf < 4; nf++) {
                mma_bf16(c[mf][nf], ah[mf][0], ah[mf][1], ah[mf][2], ah[mf][3],
                         bh[nf][0], bh[nf][1]);
                mma_bf16(c[mf][nf], al[mf][0], al[mf][1], al[mf][2], al[mf][3],
                         bh[nf][0], bh[nf][1]);
                mma_bf16(c[mf][nf], ah[mf][0], ah[mf][1], ah[mf][2], ah[mf][3],
                         bl[nf][0], bl[nf][1]);
            }
        __syncthreads();
    }

    const int Nw = N >> 1;
    #pragma unroll
    for (int mf = 0; mf < 4; mf++) {
        #pragma unroll
        for (int nf = 0; nf < 4; nf++) {
            const int row0 = crow + wrow + mf * 16 + g;
            const int col0 = ccol + wcol + nf * 8 + t4 * 2;
            float v0 = c[mf][nf][0] + bias[col0];
            float v1 = c[mf][nf][1] + bias[col0 + 1];
            float v2 = c[mf][nf][2] + bias[col0];
            float v3 = c[mf][nf][3] + bias[col0 + 1];
            if (do_relu) {
                v0 = fmaxf(v0, 0.0f); v1 = fmaxf(v1, 0.0f);
                v2 = fmaxf(v2, 0.0f); v3 = fmaxf(v3, 0.0f);
            }
            if (res) {
                const float2 r0 = *reinterpret_cast<const float2*>(
                    res + (size_t)row0 * N + col0);
                const float2 r1 = *reinterpret_cast<const float2*>(
                    res + (size_t)(row0 + 8) * N + col0);
                v0 += r0.x; v1 += r0.y; v2 += r1.x; v3 += r1.y;
            }
            if (C) {
                *reinterpret_cast<float2*>(C + (size_t)row0 * N + col0)       = make_float2(v0, v1);
                *reinterpret_cast<float2*>(C + (size_t)(row0 + 8) * N + col0) = make_float2(v2, v3);
            }
            if (Ch) {
                __nv_bfloat16 h0, l0, h1, l1, h2, l2, h3, l3;
                split_bf(v0, h0, l0); split_bf(v1, h1, l1);
                split_bf(v2, h2, l2); split_bf(v3, h3, l3);
                Ch[(size_t)row0 * Nw + (col0 >> 1)]       = pack2(h0, h1);
                Ch[(size_t)(row0 + 8) * Nw + (col0 >> 1)] = pack2(h2, h3);
                if (Cl) {
                    Cl[(size_t)row0 * Nw + (col0 >> 1)]       = pack2(l0, l1);
                    Cl[(size_t)(row0 + 8) * Nw + (col0 >> 1)] = pack2(l2, l3);
                }
            }
        }
    }
}

// ---------------------------------------------------------------------------
// Tensor-core flash attention.
// CTA: 64 q rows, 4 warps (16 rows each), Bc=64 keys/iter, DK=64.
// Q,K split bf16 (3-product QK); P split in regs, V plain bf16 (2-product PV).
// Smem rows padded to 36 words (16B-aligned, conflict-free frag reads).
// ---------------------------------------------------------------------------
#define AST 36

__global__ __launch_bounds__(128)
void attn_mma_k(const uint32_t* __restrict__ qh, const uint32_t* __restrict__ ql,
                const uint32_t* __restrict__ kh, const uint32_t* __restrict__ kl,
                const uint32_t* __restrict__ vh, const int* __restrict__ mask,
                uint32_t* __restrict__ Oh, uint32_t* __restrict__ Ol)
{
    __shared__ __align__(16) uint32_t Ksh[64 * AST];
    __shared__ __align__(16) uint32_t Ksl[64 * AST];
    __shared__ __align__(16) uint32_t Vst[64 * AST];   // transposed: [dim][key/2]
    __shared__ int masks[SS];

    const int tid  = threadIdx.x;
    const int wid  = tid >> 5;
    const int lane = tid & 31;
    const int g    = lane >> 2;
    const int t4   = lane & 3;
    const int bh   = blockIdx.y;
    const int b    = bh >> 4;
    const int h    = bh & 15;
    const int q0   = blockIdx.x * 64;
    const int wrow = wid * 16;
    const float scale = 0.125f;   // 1/sqrt(64)

    // loader mapping: id = tid + p*128; row = id&63; chunk = id>>6 (0..7)
    uint32_t sKh[4], sKl[4];
    int lro[4], lch[4];
    #pragma unroll
    for (int p = 0; p < 4; p++) {
        const int id = tid + p * 128;
        lro[p] = id & 63;
        lch[p] = id >> 6;
        sKh[p] = (uint32_t)__cvta_generic_to_shared(&Ksh[lro[p] * AST + lch[p] * 4]);
        sKl[p] = (uint32_t)__cvta_generic_to_shared(&Ksl[lro[p] * AST + lch[p] * 4]);
    }

    // preload mask row for this batch
    for (int i = tid; i < SS; i += 128) masks[i] = mask[b * SS + i];

    // ---- stage Q (hi->Ksh, lo->Ksl), then lift fragments to registers ----
    #pragma unroll
    for (int p = 0; p < 4; p++) {
        const size_t src = (size_t)(b * SS + q0 + lro[p]) * 512 + h * 32 + lch[p] * 4;
        CPA16(sKh[p], qh + src);
        CPA16(sKl[p], ql + src);
    }
    asm volatile("cp.async.commit_group;\n");
    asm volatile("cp.async.wait_group 0;\n");
    __syncthreads();

    uint32_t qfh[4][4], qfl[4][4];
    #pragma unroll
    for (int ks = 0; ks < 4; ks++) {
        const int ro = (wrow + g) * AST + ks * 8 + t4;
        qfh[ks][0] = Ksh[ro];           qfh[ks][1] = Ksh[ro + 8 * AST];
        qfh[ks][2] = Ksh[ro + 4];       qfh[ks][3] = Ksh[ro + 8 * AST + 4];
        qfl[ks][0] = Ksl[ro];           qfl[ks][1] = Ksl[ro + 8 * AST];
        qfl[ks][2] = Ksl[ro + 4];       qfl[ks][3] = Ksl[ro + 8 * AST + 4];
    }

    float acc[8][4];
    #pragma unroll
    for (int nf = 0; nf < 8; nf++)
        #pragma unroll
        for (int i = 0; i < 4; i++) acc[nf][i] = 0.0f;
    float m0 = -1e30f, m1 = -1e30f, l0 = 0.0f, l1 = 0.0f;

    uint16_t* V16 = reinterpret_cast<uint16_t*>(Vst);

    for (int kt = 0; kt < SS / 64; kt++) {
        __syncthreads();   // previous compute done reading Ks/Vst (covers Q stage too)

        // K tile hi/lo via cp.async
        #pragma unroll
        for (int p = 0; p < 4; p++) {
            const size_t src = (size_t)(b * SS + kt * 64 + lro[p]) * 512 + h * 32 + lch[p] * 4;
            CPA16(sKh[p], kh + src);
            CPA16(sKl[p], kl + src);
        }
        asm volatile("cp.async.commit_group;\n");

        // V tile: load plain bf16 + transpose into Vst[dim][key]
        #pragma unroll
        for (int p = 0; p < 4; p++) {
            const int r = lro[p], ch = lch[p];
            const uint4 w = *reinterpret_cast<const uint4*>(
                vh + (size_t)(b * SS + kt * 64 + r) * 512 + h * 32 + ch * 4);
            const uint32_t ws[4] = {w.x, w.y, w.z, w.w};
            #pragma unroll
            for (int j = 0; j < 4; j++) {
                const int ww = ch * 4 + j;          // word -> dims 2ww, 2ww+1
                V16[(2 * ww) * (2 * AST) + r]     = (uint16_t)(ws[j] & 0xffffu);
                V16[(2 * ww + 1) * (2 * AST) + r] = (uint16_t)(ws[j] >> 16);
            }
        }
        asm volatile("cp.async.wait_group 0;\n");
        __syncthreads();

        // ---- QK^T: scores 16x64 per warp (3 split products) ----
        float sc[8][4];
        #pragma unroll
        for (int nf = 0; nf < 8; nf++)
            #pragma unroll
            for (int i = 0; i < 4; i++) sc[nf][i] = 0.0f;

        #pragma unroll
        for (int ks = 0; ks < 4; ks++) {
            #pragma unroll
            for (int nf = 0; nf < 8; nf++) {
                const int bo = (nf * 8 + g) * AST + ks * 8 + t4;
                const uint32_t kb0 = Ksh[bo], kb1 = Ksh[bo + 4];
                const uint32_t kc0 = Ksl[bo], kc1 = Ksl[bo + 4];
                mma_bf16(sc[nf], qfh[ks][0], qfh[ks][1], qfh[ks][2], qfh[ks][3], kb0, kb1);
                mma_bf16(sc[nf], qfl[ks][0], qfl[ks][1], qfl[ks][2], qfl[ks][3], kb0, kb1);
                mma_bf16(sc[nf], qfh[ks][0], qfh[ks][1], qfh[ks][2], qfh[ks][3], kc0, kc1);
            }
        }

        // mask + scale
        #pragma unroll
        for (int nf = 0; nf < 8; nf++) {
            const int c0 = kt * 64 + nf * 8 + 2 * t4;
            const int ma = masks[c0], mb = masks[c0 + 1];
            sc[nf][0] = ma ? sc[nf][0] * scale : -1e9f;
            sc[nf][1] = mb ? sc[nf][1] * scale : -1e9f;
            sc[nf][2] = ma ? sc[nf][2] * scale : -1e9f;
            sc[nf][3] = mb ? sc[nf][3] * scale : -1e9f;
        }

        // online softmax: row g (vals 0,1), row g+8 (vals 2,3); reduce over t4
        float mt0 = -1e30f, mt1 = -1e30f;
        #pragma unroll
        for (int nf = 0; nf < 8; nf++) {
            mt0 = fmaxf(mt0, fmaxf(sc[nf][0], sc[nf][1]));
            mt1 = fmaxf(mt1, fmaxf(sc[nf][2], sc[nf][3]));
        }
        mt0 = fmaxf(mt0, __shfl_xor_sync(0xffffffffu, mt0, 1));
        mt0 = fmaxf(mt0, __shfl_xor_sync(0xffffffffu, mt0, 2));
        mt1 = fmaxf(mt1, __shfl_xor_sync(0xffffffffu, mt1, 1));
        mt1 = fmaxf(mt1, __shfl_xor_sync(0xffffffffu, mt1, 2));
        const float mn0 = fmaxf(m0, mt0), mn1 = fmaxf(m1, mt1);
        const float cr0 = expf(m0 - mn0), cr1 = expf(m1 - mn1);
        float ps0 = 0.0f, ps1 = 0.0f;
        #pragma unroll
        for (int nf = 0; nf < 8; nf++) {
            sc[nf][0] = expf(sc[nf][0] - mn0); ps0 += sc[nf][0];
            sc[nf][1] = expf(sc[nf][1] - mn0); ps0 += sc[nf][1];
            sc[nf][2] = expf(sc[nf][2] - mn1); ps1 += sc[nf][2];
            sc[nf][3] = expf(sc[nf][3] - mn1); ps1 += sc[nf][3];
        }
        ps0 += __shfl_xor_sync(0xffffffffu, ps0, 1);
        ps0 += __shfl_xor_sync(0xffffffffu, ps0, 2);
        ps1 += __shfl_xor_sync(0xffffffffu, ps1, 1);
        ps1 += __shfl_xor_sync(0xffffffffu, ps1, 2);
        l0 = l0 * cr0 + ps0;  m0 = mn0;
        l1 = l1 * cr1 + ps1;  m1 = mn1;
        #pragma unroll
        for (int nf = 0; nf < 8; nf++) {
            acc[nf][0] *= cr0; acc[nf][1] *= cr0;
            acc[nf][2] *= cr1; acc[nf][3] *= cr1;
        }

        // ---- PV: split P (hi/lo) x plain V (2 products) ----
        #pragma unroll
        for (int kc = 0; kc < 4; kc++) {
            __nv_bfloat16 h0, e0, h1, e1, h2, e2, h3, e3, h4, e4, h5, e5, h6, e6, h7, e7;
            split_bf(sc[2*kc][0],   h0, e0); split_bf(sc[2*kc][1],   h1, e1);
            split_bf(sc[2*kc][2],   h2, e2); split_bf(sc[2*kc][3],   h3, e3);
            split_bf(sc[2*kc+1][0], h4, e4); split_bf(sc[2*kc+1][1], h5, e5);
            split_bf(sc[2*kc+1][2], h6, e6); split_bf(sc[2*kc+1][3], h7, e7);
            const uint32_t pa0 = pack2(h0, h1), pa1 = pack2(h2, h3);
            const uint32_t pa2 = pack2(h4, h5), pa3 = pack2(h6, h7);
            const uint32_t pb0 = pack2(e0, e1), pb1 = pack2(e2, e3);
            const uint32_t pb2 = pack2(e4, e5), pb3 = pack2(e6, e7);
            #pragma unroll
            for (int nf = 0; nf < 8; nf++) {
                const int vo = (nf * 8 + g) * AST + kc * 8 + t4;
                const uint32_t vb0 = Vst[vo], vb1 = Vst[vo + 4];
                mma_bf16(acc[nf], pa0, pa1, pa2, pa3, vb0, vb1);
                mma_bf16(acc[nf], pb0, pb1, pb2, pb3, vb0, vb1);
            }
        }
    }

    // ---- normalize + write split-bf16 ctx ----
    const float in0 = 1.0f / l0, in1 = 1.0f / l1;
    const size_t r0 = (size_t)(b * SS + q0 + wrow + g) * 512 + h * 32;
    const size_t r1 = (size_t)(b * SS + q0 + wrow + g + 8) * 512 + h * 32;
    #pragma unroll
    for (int nf = 0; nf < 8; nf++) {
        const int w = nf * 4 + t4;
        __nv_bfloat16 h0, e0, h1, e1, h2, e2, h3, e3;
        split_bf(acc[nf][0] * in0, h0, e0); split_bf(acc[nf][1] * in0, h1, e1);
        split_bf(acc[nf][2] * in1, h2, e2); split_bf(acc[nf][3] * in1, h3, e3);
        Oh[r0 + w] = pack2(h0, h1);  Ol[r0 + w] = pack2(e0, e1);
        Oh[r1 + w] = pack2(h2, h3);  Ol[r1 + w] = pack2(e2, e3);
    }
}

// ---------------------------------------------------------------------------
// Launch
// ---------------------------------------------------------------------------
extern "C" void kernel_launch(void* const* d_in, const int* in_sizes, int n_in,
                              void* d_out, int out_size)
{
    const float* x      = (const float*)d_in[0];
    const int*   mask   = (const int*)  d_in[1];
    const float* wq     = (const float*)d_in[2];
    const float* bq     = (const float*)d_in[3];
    const float* wk     = (const float*)d_in[4];
    const float* bk     = (const float*)d_in[5];
    const float* wv     = (const float*)d_in[6];
    const float* bv     = (const float*)d_in[7];
    const float* wo     = (const float*)d_in[8];
    const float* bo     = (const float*)d_in[9];
    const float* w1     = (const float*)d_in[10];
    const float* b1     = (const float*)d_in[11];
    const float* w2     = (const float*)d_in[12];
    const float* b2     = (const float*)d_in[13];
    const float* alpha1 = (const float*)d_in[14];
    const float* beta1  = (const float*)d_in[15];
    const float* alpha2 = (const float*)d_in[16];
    const float* beta2  = (const float*)d_in[17];
    float* out = (float*)d_out;

    uint32_t *xnh, *xnl, *qhp, *qlp, *khp, *klp, *vhp, *ctxh, *ctxl;
    uint32_t *xn2h, *xn2l, *hh, *hl;
    uint32_t *wqth, *wqtl, *wkth, *wktl, *wvth, *wvtl, *woth, *wotl;
    uint32_t *w1th, *w1tl, *w2th, *w2tl;
    cudaGetSymbolAddress((void**)&xnh,  g_xn_h);
    cudaGetSymbolAddress((void**)&xnl,  g_xn_l);
    cudaGetSymbolAddress((void**)&qhp,  g_q_h);
    cudaGetSymbolAddress((void**)&qlp,  g_q_l);
    cudaGetSymbolAddress((void**)&khp,  g_k_h);
    cudaGetSymbolAddress((void**)&klp,  g_k_l);
    cudaGetSymbolAddress((void**)&vhp,  g_v_h);
    cudaGetSymbolAddress((void**)&ctxh, g_ctx_h);
    cudaGetSymbolAddress((void**)&ctxl, g_ctx_l);
    cudaGetSymbolAddress((void**)&xn2h, g_xn2_h);
    cudaGetSymbolAddress((void**)&xn2l, g_xn2_l);
    cudaGetSymbolAddress((void**)&hh,   g_h_h);
    cudaGetSymbolAddress((void**)&hl,   g_h_l);
    cudaGetSymbolAddress((void**)&wqth, g_wqt_h);
    cudaGetSymbolAddress((void**)&wqtl, g_wqt_l);
    cudaGetSymbolAddress((void**)&wkth, g_wkt_h);
    cudaGetSymbolAddress((void**)&wktl, g_wkt_l);
    cudaGetSymbolAddress((void**)&wvth, g_wvt_h);
    cudaGetSymbolAddress((void**)&wvtl, g_wvt_l);
    cudaGetSymbolAddress((void**)&woth, g_wot_h);
    cudaGetSymbolAddress((void**)&wotl, g_wot_l);
    cudaGetSymbolAddress((void**)&w1th, g_w1t_h);
    cudaGetSymbolAddress((void**)&w1tl, g_w1t_l);
    cudaGetSymbolAddress((void**)&w2th, g_w2t_h);
    cudaGetSymbolAddress((void**)&w2tl, g_w2t_l);

    // 0. weight prep
    wprep_k<<<dim3(DD / 32, DD / 32), 256>>>(wq, wqth, wqtl, DD, DD);
    wprep_k<<<dim3(DD / 32, DD / 32), 256>>>(wk, wkth, wktl, DD, DD);
    wprep_k<<<dim3(DD / 32, DD / 32), 256>>>(wv, wvth, wvtl, DD, DD);
    wprep_k<<<dim3(DD / 32, DD / 32), 256>>>(wo, woth, wotl, DD, DD);
    wprep_k<<<dim3(DFF / 32, DD / 32), 256>>>(w1, w1th, w1tl, DD, DFF);
    wprep_k<<<dim3(DD / 32, DFF / 32), 256>>>(w2, w2th, w2tl, DFF, DD);

    // 1. LN1 -> split
    layernorm_k<<<MM, 256>>>(x, xnh, xnl, alpha1, beta1);

    // 2-4. Q,K (split bf16 out), V (plain bf16 out)
    dim3 gP(DD / 128, MM / 128);
    gemm_bf16_k<<<gP, 256>>>(xnh, xnl, wqth, wqtl, bq, nullptr, nullptr, qhp, qlp, DD, DD, 0);
    gemm_bf16_k<<<gP, 256>>>(xnh, xnl, wkth, wktl, bk, nullptr, nullptr, khp, klp, DD, DD, 0);
    gemm_bf16_k<<<gP, 256>>>(xnh, xnl, wvth, wvtl, bv, nullptr, nullptr, vhp, nullptr, DD, DD, 0);

    // 5. tensor-core attention -> split ctx
    attn_mma_k<<<dim3(SS / 64, BB * HH), 128>>>(qhp, qlp, khp, klp, vhp, mask, ctxh, ctxl);

    // 6. output projection + residual -> out (fp32)
    gemm_bf16_k<<<gP, 256>>>(ctxh, ctxl, woth, wotl, bo, x, out, nullptr, nullptr, DD, DD, 0);

    // 7. LN2 -> split
    layernorm_k<<<MM, 256>>>(out, xn2h, xn2l, alpha2, beta2);

    // 8. FFN1 + ReLU -> split
    gemm_bf16_k<<<dim3(DFF / 128, MM / 128), 256>>>(xn2h, xn2l, w1th, w1tl, b1, nullptr,
                                                    nullptr, hh, hl, DFF, DD, 1);

    // 9. FFN2 + residual
    gemm_bf16_k<<<gP, 256>>>(hh, hl, w2th, w2tl, b2, out, out, nullptr, nullptr, DD, DFF, 0);
}